// round 3
// baseline (speedup 1.0000x reference)
#include <cuda_runtime.h>

// Problem constants: B=32, S=12, F=128, H=64, K=8, C=64, N=512
#define B_    32
#define S_    12
#define F_    128
#define H_    64
#define K_    8
#define C_    64
#define N_    512
#define KH_   (K_*H_)        // 512
#define WFC_  (N_*C_)        // 32768 floats per Wf row
#define NWFB  128            // Wf blocks: 2 per row (64KB chunks)
#define NWHO  B_             // 32 Who blocks
#define NBLK  (NWFB + NWHO)  // 160 total

// Scratch (device globals; no mallocs). g_count zero at load, reset in-kernel.
__device__ float g_Who[B_*C_];          // 2048
__device__ float g_part[NWFB*C_];       // 8192
__device__ unsigned int g_count;        // zero-init

__global__ __launch_bounds__(1024) void k_fused(
    const float* __restrict__ x,        // (B, S, F)
    const float* __restrict__ W_heads,  // (K, F, H)
    const float* __restrict__ W_out,    // (K*H, C)
    const float* __restrict__ Wf,       // (C, N*C)
    const float* __restrict__ bf,       // (C,)
    float* __restrict__ out)            // (B, C)
{
    // one shared buffer, aliased per phase (max: epilogue 6208 floats)
    __shared__ __align__(16) float sm[6272];
    __shared__ unsigned int s_last;

    const int t   = threadIdx.x;
    const int bid = blockIdx.x;

    if (bid < NWFB) {
        // ---- Wf half-row reduction: 64KB contiguous per block ----
        const int cp    = bid >> 1;
        const int chunk = bid & 1;
        const float4* __restrict__ p4 =
            (const float4*)(Wf + (size_t)cp * WFC_) + chunk * 4096;
        float4 s = make_float4(0.f, 0.f, 0.f, 0.f);
        #pragma unroll
        for (int i = 0; i < 4; ++i) {                 // 4 independent float4 loads
            float4 v = p4[t + i * 1024];
            s.x += v.x; s.y += v.y; s.z += v.z; s.w += v.w;
        }
        float4* part4 = (float4*)sm;
        part4[t] = s;
        __syncthreads();
        if (t < C_) {
            // float view: sm[n*64 + c], 64 n-groups
            float acc = 0.f;
            #pragma unroll
            for (int n = 0; n < 64; ++n) acc += sm[n * 64 + t];
            g_part[bid * C_ + t] = acc;
        }
    } else {
        // ---- Who[b,:] : GAT collapse (softmax over identical rows is uniform,
        //      so att @ Wh == Wh for both GAT layers) ----
        float* xs   = sm;                 // 128
        float* ws   = sm + 128;           // 1024
        float* hcat = sm + 128 + 1024;    // 512
        const int b = bid - NWFB;
        if (t < F_) xs[t] = x[(b * S_ + (S_ - 1)) * F_ + t];
        __syncthreads();
        {   // Wh[k,h], each output split across 2 threads (64 f's each)
            const int o    = t & 511;
            const int half = t >> 9;
            const int k    = o >> 6;
            const int h    = o & 63;
            const float* wp = W_heads + ((size_t)k * F_ + half * 64) * H_ + h;
            const float* xp = xs + half * 64;
            float acc = 0.f;
            #pragma unroll 8
            for (int f = 0; f < 64; ++f) acc = fmaf(xp[f], wp[(size_t)f * H_], acc);
            ws[t] = acc;
        }
        __syncthreads();
        if (t < KH_) {
            float v = ws[t] + ws[t + 512];
            hcat[t] = v > 0.f ? v : expm1f(v);        // ELU
        }
        __syncthreads();
        {   // Who[c] = sum_j hcat[j] * W_out[j,c], j split 16 ways
            const int c  = t & 63;
            const int j0 = t >> 6;
            float p = 0.f;
            #pragma unroll
            for (int j = j0; j < KH_; j += 16)
                p = fmaf(hcat[j], W_out[(size_t)j * C_ + c], p);
            ws[t] = p;
        }
        __syncthreads();
        if (t < C_) {
            float s2 = 0.f;
            #pragma unroll
            for (int g = 0; g < 16; ++g) s2 += ws[g * 64 + t];
            g_Who[b * C_ + t] = s2;
        }
    }

    // ---- arrival counter: last block runs the epilogue ----
    __syncthreads();
    if (t == 0) {
        __threadfence();
        unsigned int old = atomicAdd(&g_count, 1u);
        s_last = (old == NBLK - 1) ? 1u : 0u;
    }
    __syncthreads();
    if (!s_last) return;
    __threadfence();   // acquire: make other blocks' writes visible

    // ---- epilogue: fold partials, tiny GEMV ----
    float* wfs   = sm;            // 64 rows x 65 (padded) = 4160
    float* who_s = sm + 4160;     // 2048
    #pragma unroll
    for (int i = t; i < C_ * C_; i += 1024) {
        const int cp = i >> 6, c = i & 63;
        wfs[cp * 65 + c] = __ldcg(&g_part[(cp * 2) * C_ + c]) +
                           __ldcg(&g_part[(cp * 2 + 1) * C_ + c]);
    }
    who_s[t]        = __ldcg(&g_Who[t]);
    who_s[t + 1024] = __ldcg(&g_Who[t + 1024]);
    __syncthreads();

    #pragma unroll
    for (int rep = 0; rep < 2; ++rep) {
        const int idx = t + rep * 1024;
        const int b = idx >> 6, cp = idx & 63;
        float acc = bf[cp];
        const float* hr = who_s + b * C_;
        const float* wr = wfs + cp * 65;
        #pragma unroll 8
        for (int c = 0; c < C_; ++c) acc = fmaf(hr[c], wr[c], acc);
        out[idx] = acc;
    }

    if (t == 0) g_count = 0;   // reset for next graph replay (deterministic)
}

extern "C" void kernel_launch(void* const* d_in, const int* in_sizes, int n_in,
                              void* d_out, int out_size)
{
    const float* x       = (const float*)d_in[0]; // (32,12,128)
    const float* W_heads = (const float*)d_in[1]; // (8,128,64)
    // d_in[2], d_in[3]: a1_heads/a2_heads — unused (uniform softmax)
    const float* W_out   = (const float*)d_in[4]; // (512,64)
    // d_in[5], d_in[6]: a1_out/a2_out — unused
    const float* Wf      = (const float*)d_in[7]; // (64, 32768)
    const float* bf      = (const float*)d_in[8]; // (64,)
    float* out = (float*)d_out;                   // (32,64)

    k_fused<<<NBLK, 1024>>>(x, W_heads, W_out, Wf, bf, out);
}

// round 4
// speedup vs baseline: 1.1324x; 1.1324x over previous
#include <cuda_runtime.h>

// Problem constants: B=32, S=12, F=128, H=64, K=8, C=64, N=512
#define B_   32
#define S_   12
#define F_   128
#define H_   64
#define K_   8
#define C_   64
#define N_   512
#define KH_  (K_*H_)        // 512
#define WFC_ (N_*C_)        // 32768 floats per Wf row

// Scratch (no device mallocs allowed):
__device__ float g_Who[B_*C_];     // 2048 floats
__device__ float g_wfs[C_*C_];     // WfSum[c'][c], 4096 floats

// Kernel 1 (unchanged from best-known config), 96 blocks x 1024 threads:
//  blocks [0,64):  WfSum[c',:] — each block streams one full 128KB Wf row
//  blocks [64,96): Who[b,:]    — GAT collapse (uniform softmax => att@Wh == Wh)
__global__ __launch_bounds__(1024) void k1(
    const float* __restrict__ x,        // (B, S, F)
    const float* __restrict__ W_heads,  // (K, F, H)
    const float* __restrict__ W_out,    // (K*H, C)
    const float* __restrict__ Wf)       // (C, N*C)
{
    const int t   = threadIdx.x;
    const int bid = blockIdx.x;

    if (bid < C_) {
        // ---- Wf row reduction: the only DRAM-heavy work (8.4 MB total) ----
        __shared__ float4 part4[1024];          // 16 KB
        const int cp = bid;
        const int c4 = t & 15;                  // which float4 within a 64-float n-row
        const int n0 = t >> 4;                  // 0..63
        const float4* __restrict__ row = (const float4*)(Wf + (size_t)cp * WFC_);
        float4 s = make_float4(0.f, 0.f, 0.f, 0.f);
        #pragma unroll
        for (int i = 0; i < 8; ++i) {           // 8 independent float4 loads
            float4 v = row[(size_t)(n0 + i * 64) * 16 + c4];
            s.x += v.x; s.y += v.y; s.z += v.z; s.w += v.w;
        }
        part4[t] = s;
        __syncthreads();
        if (t < C_) {
            const float* pf = (const float*)part4;
            float acc = 0.f;
            #pragma unroll
            for (int n0i = 0; n0i < 64; ++n0i) acc += pf[n0i * 64 + t];
            g_wfs[cp * C_ + t] = acc;
        }
    } else {
        // ---- Who[b,:] ----
        __shared__ float xs[F_];
        __shared__ float ws[1024];
        __shared__ float hcat[KH_];
        const int b = bid - C_;
        if (t < F_) xs[t] = x[(b * S_ + (S_ - 1)) * F_ + t];
        __syncthreads();
        {
            const int o    = t & 511;
            const int half = t >> 9;
            const int k    = o >> 6;
            const int h    = o & 63;
            const float* wp = W_heads + ((size_t)k * F_ + half * 64) * H_ + h;
            const float* xp = xs + half * 64;
            float acc = 0.f;
            #pragma unroll 8
            for (int f = 0; f < 64; ++f) acc = fmaf(xp[f], wp[(size_t)f * H_], acc);
            ws[t] = acc;
        }
        __syncthreads();
        if (t < KH_) {
            float v = ws[t] + ws[t + 512];
            hcat[t] = v > 0.f ? v : expm1f(v);   // ELU
        }
        __syncthreads();
        {
            const int c  = t & 63;
            const int j0 = t >> 6;
            float p = 0.f;
            #pragma unroll
            for (int j = j0; j < KH_; j += 16) p = fmaf(hcat[j], W_out[(size_t)j * C_ + c], p);
            ws[t] = p;
        }
        __syncthreads();
        if (t < C_) {
            float s2 = 0.f;
            #pragma unroll
            for (int g = 0; g < 16; ++g) s2 += ws[g * 64 + t];
            g_Who[b * C_ + t] = s2;
        }
    }
}

// Kernel 2: barrier-free, smem-free. 8 blocks x 256 threads = 2048 threads,
// one output element each. 32 independent float4 L2 loads per thread, then a
// short unrolled FMA reduction. Critical path ~= one L2 round trip.
__global__ __launch_bounds__(256) void k2(
    const float* __restrict__ bf,
    float* __restrict__ out)
{
    const int idx = blockIdx.x * 256 + threadIdx.x;   // 0..2047
    const int b   = idx >> 6;
    const int cp  = idx & 63;

    const float4* __restrict__ w4 = ((const float4*)g_wfs) + cp * 16;
    const float4* __restrict__ h4 = ((const float4*)g_Who) + b * 16;

    float a0 = 0.f, a1 = 0.f, a2 = 0.f, a3 = 0.f;
    #pragma unroll
    for (int i = 0; i < 16; ++i) {
        const float4 w = w4[i];
        const float4 h = h4[i];
        a0 = fmaf(h.x, w.x, a0);
        a1 = fmaf(h.y, w.y, a1);
        a2 = fmaf(h.z, w.z, a2);
        a3 = fmaf(h.w, w.w, a3);
    }
    out[idx] = bf[cp] + ((a0 + a1) + (a2 + a3));
}

extern "C" void kernel_launch(void* const* d_in, const int* in_sizes, int n_in,
                              void* d_out, int out_size)
{
    const float* x       = (const float*)d_in[0]; // (32,12,128)
    const float* W_heads = (const float*)d_in[1]; // (8,128,64)
    // d_in[2], d_in[3]: a1_heads/a2_heads — unused (uniform softmax)
    const float* W_out   = (const float*)d_in[4]; // (512,64)
    // d_in[5], d_in[6]: a1_out/a2_out — unused
    const float* Wf      = (const float*)d_in[7]; // (64, 32768)
    const float* bf      = (const float*)d_in[8]; // (64,)
    float* out = (float*)d_out;                   // (32,64)

    k1<<<C_ + B_, 1024>>>(x, W_heads, W_out, Wf);
    k2<<<8, 256>>>(bf, out);
}